// round 4
// baseline (speedup 1.0000x reference)
#include <cuda_runtime.h>
#include <stdint.h>

#define BATCH 128
#define NQ    2000
#define NC    3
#define QC    6000
#define NV4   1500          // QC/4
#define TOPK  100
#define NP    20
#define NT    512
#define NJ4   3             // ceil(NV4/NT)
#define NKEY  (NJ4 * 4)     // 12 keys/thread
#define CAND_CAP 2048

// Output layout (float32, reference tuple order, flattened):
#define OFF_BOXES  0
#define OFF_SCORES 51200
#define OFF_LABELS 64000
#define OFF_PTS    76800
#define OFF_MASK   588800

__global__ __launch_bounds__(NT, 1)
void maptr_post_kernel(const float* __restrict__ cls,
                       const float* __restrict__ bbox,
                       const float* __restrict__ pts,
                       float* __restrict__ out)
{
    __shared__ unsigned long long cand[CAND_CAP];     // 16 KB
    __shared__ unsigned int       warp_cnt[NT / 32];
    __shared__ int                n_cand;

    const int b    = blockIdx.x;
    const int t    = threadIdx.x;
    const int wid  = t >> 5;
    const int lane = t & 31;

    if (t == 0) n_cand = 0;

    // ---- pass 1: float4 loads -> 12 monotone keys in registers ----
    const float4* logit4 = (const float4*)(cls + (size_t)(5 * BATCH + b) * QC);
    unsigned int key[NKEY];
#pragma unroll
    for (int v = 0; v < NJ4; v++) {
        const int idx4 = t + v * NT;
        unsigned int m0 = 0u, m1 = 0u, m2 = 0u, m3 = 0u;
        if (idx4 < NV4) {
            float4 w = logit4[idx4];
            unsigned int u;
            u = __float_as_uint(w.x); m0 = (u & 0x80000000u) ? ~u : (u | 0x80000000u);
            u = __float_as_uint(w.y); m1 = (u & 0x80000000u) ? ~u : (u | 0x80000000u);
            u = __float_as_uint(w.z); m2 = (u & 0x80000000u) ? ~u : (u | 0x80000000u);
            u = __float_as_uint(w.w); m3 = (u & 0x80000000u) ? ~u : (u | 0x80000000u);
        }
        key[v * 4 + 0] = m0; key[v * 4 + 1] = m1;
        key[v * 4 + 2] = m2; key[v * 4 + 3] = m3;
    }

    // ---- binary search on 12-bit bin space for the cutoff ----
    // f(B) = #{key >= B<<20} is non-increasing; find max B with f(B) >= TOPK.
    int lo = 1, hi = 4095;          // f(1) ~ all-positive keys >> TOPK, invariant holds
    while (lo < hi) {
        const int mid = (lo + hi + 1) >> 1;
        const unsigned int T = ((unsigned int)mid) << 20;
        unsigned int c = 0u;
#pragma unroll
        for (int j = 0; j < NKEY; j++) c += (key[j] >= T);
        c = __reduce_add_sync(0xFFFFFFFFu, c);
        if (lane == 0) warp_cnt[wid] = c;
        __syncthreads();
        unsigned int tot = 0u;
#pragma unroll
        for (int i = 0; i < NT / 32; i++) tot += warp_cnt[i];
        __syncthreads();                 // protect warp_cnt before next iteration
        if (tot >= TOPK) lo = mid; else hi = mid - 1;
    }
    const unsigned int keycut = ((unsigned int)lo) << 20;

    // ---- pass 2: warp-aggregated candidate collection ----
#pragma unroll
    for (int v = 0; v < NJ4; v++) {
        const int idx4 = t + v * NT;
#pragma unroll
        for (int c = 0; c < 4; c++) {
            const unsigned int k = key[v * 4 + c];
            const bool pred = (k >= keycut) && (k != 0u);
            const unsigned int mask = __ballot_sync(0xFFFFFFFFu, pred);
            if (mask) {
                int base;
                if (lane == 0) base = atomicAdd(&n_cand, __popc(mask));
                base = __shfl_sync(0xFFFFFFFFu, base, 0);
                if (pred) {
                    int off = __popc(mask & ((1u << lane) - 1u));
                    int p = base + off;
                    if (p < CAND_CAP)
                        cand[p] = ((unsigned long long)k << 32) |
                                  (unsigned int)(0xFFFFFFFFu - (unsigned int)(idx4 * 4 + c));
                }
            }
        }
    }
    __syncthreads();
    const int C = (n_cand < CAND_CAP) ? n_cand : CAND_CAP;

    // ---- exact rank among candidates; rank<TOPK decodes + gathers directly ----
    const float*  bbp = bbox + (size_t)(5 * BATCH + b) * NQ * 4;
    const float4* pp4 = (const float4*)(pts + (size_t)(5 * BATCH + b) * NQ * NP * 2);
    float4*       op4 = (float4*)(out + OFF_PTS + (size_t)b * TOPK * NP * 2);

    for (int i = t; i < C; i += NT) {
        const unsigned long long me = cand[i];
        int rank = 0;
        int jj = 0;
        for (; jj + 4 <= C; jj += 4) {
            rank += (cand[jj]     > me);
            rank += (cand[jj + 1] > me);
            rank += (cand[jj + 2] > me);
            rank += (cand[jj + 3] > me);
        }
        for (; jj < C; jj++) rank += (cand[jj] > me);

        if (rank < TOPK) {
            unsigned int mono = (unsigned int)(me >> 32);
            unsigned int u = (mono & 0x80000000u) ? (mono ^ 0x80000000u) : ~mono;
            float f = __uint_as_float(u);
            float score = 1.0f / (1.0f + expf(-f));
            int   g   = (int)(0xFFFFFFFFu - (unsigned int)me);
            int   bi  = g / NC;
            int   lab = g - bi * NC;

            float4 bv = *(const float4*)(bbp + (size_t)bi * 4);
            float x1 = (bv.x - 0.5f * bv.z) * 30.0f - 15.0f;
            float y1 = (bv.y - 0.5f * bv.w) * 60.0f - 30.0f;
            float x2 = (bv.x + 0.5f * bv.z) * 30.0f - 15.0f;
            float y2 = (bv.y + 0.5f * bv.w) * 60.0f - 30.0f;

            bool mk = (x1 >= -20.0f) && (y1 >= -35.0f) && (x2 >= -20.0f) && (y2 >= -35.0f) &&
                      (x1 <=  20.0f) && (y1 <=  35.0f) && (x2 <=  20.0f) && (y2 <=  35.0f);

            if (!mk) { x1 = y1 = x2 = y2 = 0.0f; }
            float* ob = out + OFF_BOXES + (size_t)(b * TOPK + rank) * 4;
            ob[0] = x1; ob[1] = y1; ob[2] = x2; ob[3] = y2;
            out[OFF_SCORES + b * TOPK + rank] = mk ? score : 0.0f;
            out[OFF_LABELS + b * TOPK + rank] = mk ? (float)lab : -1.0f;
            out[OFF_MASK   + b * TOPK + rank] = mk ? 1.0f : 0.0f;

            // fused pts gather: 40 floats = 10 float4 per selection
            const float4* src = pp4 + (size_t)bi * (NP * 2 / 4);
            float4*       dst = op4 + (size_t)rank * (NP * 2 / 4);
            if (mk) {
#pragma unroll
                for (int q = 0; q < NP * 2 / 4; q++) {
                    float4 r = src[q];
                    r.x = r.x * 30.0f - 15.0f;
                    r.y = r.y * 60.0f - 30.0f;
                    r.z = r.z * 30.0f - 15.0f;
                    r.w = r.w * 60.0f - 30.0f;
                    dst[q] = r;
                }
            } else {
                float4 z = make_float4(0.0f, 0.0f, 0.0f, 0.0f);
#pragma unroll
                for (int q = 0; q < NP * 2 / 4; q++) dst[q] = z;
            }
        }
    }
}

extern "C" void kernel_launch(void* const* d_in, const int* in_sizes, int n_in,
                              void* d_out, int out_size)
{
    const float* cls = nullptr;
    const float* bb  = nullptr;
    const float* pt  = nullptr;
    for (int i = 0; i < n_in; i++) {
        if      (in_sizes[i] == 4608000)  cls = (const float*)d_in[i];
        else if (in_sizes[i] == 6144000)  bb  = (const float*)d_in[i];
        else if (in_sizes[i] == 61440000) pt  = (const float*)d_in[i];
    }
    if (!cls && n_in > 0) cls = (const float*)d_in[0];
    if (!bb  && n_in > 1) bb  = (const float*)d_in[1];
    if (!pt  && n_in > 2) pt  = (const float*)d_in[2];

    maptr_post_kernel<<<BATCH, NT>>>(cls, bb, pt, (float*)d_out);
    (void)out_size;
}

// round 5
// speedup vs baseline: 1.0025x; 1.0025x over previous
#include <cuda_runtime.h>
#include <stdint.h>

#define BATCH 128
#define NQ    2000
#define NC    3
#define QC    6000
#define NV4   1500          // QC/4
#define TOPK  100
#define NP    20
#define NPQ   (NP * 2 / 4)  // 10 float4 per selection
#define NT    512
#define NJ4   3             // ceil(NV4/NT)
#define NBINS 4096
#define BPT   8             // NBINS/NT bins per thread in scan
#define CAND_CAP 1024

// Output layout (float32, reference tuple order, flattened):
#define OFF_BOXES  0
#define OFF_SCORES 51200
#define OFF_LABELS 64000
#define OFF_PTS    76800
#define OFF_MASK   588800

__global__ __launch_bounds__(NT, 1)
void maptr_post_kernel(const float* __restrict__ cls,
                       const float* __restrict__ bbox,
                       const float* __restrict__ pts,
                       float* __restrict__ out)
{
    __shared__ unsigned int       hist[NBINS];        // 16 KB
    __shared__ unsigned long long cand[CAND_CAP];     // 8 KB
    __shared__ int                n_cand;
    __shared__ unsigned int       warp_tot[NT / 32];
    __shared__ int                sh_bcut;

    const int b    = blockIdx.x;
    const int t    = threadIdx.x;
    const int wid  = t >> 5;
    const int lane = t & 31;

    for (int i = t; i < NBINS; i += NT) hist[i] = 0u;
    if (t == 0) n_cand = 0;
    __syncthreads();

    // ---- pass 1: float4 loads -> monotone keys in regs + 12-bit histogram ----
    const float4* logit4 = (const float4*)(cls + (size_t)(5 * BATCH + b) * QC);
    unsigned int key[NJ4 * 4];
#pragma unroll
    for (int v = 0; v < NJ4; v++) {
        const int idx4 = t + v * NT;
        unsigned int m0 = 0u, m1 = 0u, m2 = 0u, m3 = 0u;
        if (idx4 < NV4) {
            float4 w = logit4[idx4];
            unsigned int u;
            u = __float_as_uint(w.x); m0 = (u & 0x80000000u) ? ~u : (u | 0x80000000u);
            u = __float_as_uint(w.y); m1 = (u & 0x80000000u) ? ~u : (u | 0x80000000u);
            u = __float_as_uint(w.z); m2 = (u & 0x80000000u) ? ~u : (u | 0x80000000u);
            u = __float_as_uint(w.w); m3 = (u & 0x80000000u) ? ~u : (u | 0x80000000u);
            atomicAdd(&hist[m0 >> 20], 1u);
            atomicAdd(&hist[m1 >> 20], 1u);
            atomicAdd(&hist[m2 >> 20], 1u);
            atomicAdd(&hist[m3 >> 20], 1u);
        }
        key[v * 4 + 0] = m0; key[v * 4 + 1] = m1;
        key[v * 4 + 2] = m2; key[v * 4 + 3] = m3;
    }
    __syncthreads();

    // ---- suffix scan (descending bins) to find cutoff bin ----
    const int bin_hi = NBINS - 1 - BPT * t;
    unsigned int ssum = 0u;
#pragma unroll
    for (int k = 0; k < BPT; k++) ssum += hist[bin_hi - k];

    unsigned int inc = ssum;
#pragma unroll
    for (int off = 1; off < 32; off <<= 1) {
        unsigned int v = __shfl_up_sync(0xFFFFFFFFu, inc, off);
        if (lane >= off) inc += v;
    }
    if (lane == 31) warp_tot[wid] = inc;
    __syncthreads();
    unsigned int woff = 0u;
    for (int i = 0; i < wid; i++) woff += warp_tot[i];
    const unsigned int excl = woff + inc - ssum;

    if (excl < TOPK && excl + ssum >= TOPK) {      // exactly one thread
        unsigned int acc = excl;
        int bc = bin_hi;
#pragma unroll
        for (int k = 0; k < BPT; k++) {
            acc += hist[bin_hi - k];
            if (acc >= TOPK) { bc = bin_hi - k; break; }
        }
        sh_bcut = bc;
    }
    __syncthreads();
    const unsigned int keycut = ((unsigned int)sh_bcut) << 20;

    // ---- pass 2: warp-aggregated candidate collection ----
#pragma unroll
    for (int v = 0; v < NJ4; v++) {
        const int idx4 = t + v * NT;
#pragma unroll
        for (int c = 0; c < 4; c++) {
            const unsigned int k = key[v * 4 + c];
            const bool pred = (k >= keycut) && (k != 0u);
            const unsigned int mask = __ballot_sync(0xFFFFFFFFu, pred);
            if (mask) {
                int base;
                if (lane == 0) base = atomicAdd(&n_cand, __popc(mask));
                base = __shfl_sync(0xFFFFFFFFu, base, 0);
                if (pred) {
                    int p = base + __popc(mask & ((1u << lane) - 1u));
                    if (p < CAND_CAP)
                        cand[p] = ((unsigned long long)k << 32) |
                                  (unsigned int)(0xFFFFFFFFu - (unsigned int)(idx4 * 4 + c));
                }
            }
        }
    }
    __syncthreads();
    const int C = (n_cand < CAND_CAP) ? n_cand : CAND_CAP;

    const float*  bbp = bbox + (size_t)(5 * BATCH + b) * NQ * 4;
    const float4* pp4 = (const float4*)(pts + (size_t)(5 * BATCH + b) * NQ * NP * 2);
    float4*       op4 = (float4*)(out + OFF_PTS + (size_t)b * TOPK * NP * 2);

    // ---- first strip (i == t): prefetch gather data BEFORE ranking so DRAM
    //      latency overlaps the rank loop ----
    {
        const bool have = (t < C);
        const unsigned long long me = have ? cand[t] : 0ull;
        const int g  = (int)(0xFFFFFFFFu - (unsigned int)me);
        const int bi = have ? (g / NC) : 0;

        float4 bv = make_float4(0.f, 0.f, 0.f, 0.f);
        float4 p[NPQ];
        if (have) {
            bv = *(const float4*)(bbp + (size_t)bi * 4);
            const float4* src = pp4 + (size_t)bi * NPQ;
#pragma unroll
            for (int q = 0; q < NPQ; q++) p[q] = src[q];
        }

        // rank while loads are in flight (all threads participate; me=0 harmless)
        int rank = 0;
        int jj = 0;
        for (; jj + 4 <= C; jj += 4) {
            rank += (cand[jj]     > me);
            rank += (cand[jj + 1] > me);
            rank += (cand[jj + 2] > me);
            rank += (cand[jj + 3] > me);
        }
        for (; jj < C; jj++) rank += (cand[jj] > me);

        if (have && rank < TOPK) {
            unsigned int mono = (unsigned int)(me >> 32);
            unsigned int u = (mono & 0x80000000u) ? (mono ^ 0x80000000u) : ~mono;
            float f = __uint_as_float(u);
            float score = 1.0f / (1.0f + __expf(-f));
            int   lab = g - bi * NC;

            float x1 = (bv.x - 0.5f * bv.z) * 30.0f - 15.0f;
            float y1 = (bv.y - 0.5f * bv.w) * 60.0f - 30.0f;
            float x2 = (bv.x + 0.5f * bv.z) * 30.0f - 15.0f;
            float y2 = (bv.y + 0.5f * bv.w) * 60.0f - 30.0f;

            bool mk = (x1 >= -20.0f) && (y1 >= -35.0f) && (x2 >= -20.0f) && (y2 >= -35.0f) &&
                      (x1 <=  20.0f) && (y1 <=  35.0f) && (x2 <=  20.0f) && (y2 <=  35.0f);

            if (!mk) { x1 = y1 = x2 = y2 = 0.0f; }
            float* ob = out + OFF_BOXES + (size_t)(b * TOPK + rank) * 4;
            ob[0] = x1; ob[1] = y1; ob[2] = x2; ob[3] = y2;
            out[OFF_SCORES + b * TOPK + rank] = mk ? score : 0.0f;
            out[OFF_LABELS + b * TOPK + rank] = mk ? (float)lab : -1.0f;
            out[OFF_MASK   + b * TOPK + rank] = mk ? 1.0f : 0.0f;

            float4* dst = op4 + (size_t)rank * NPQ;
            if (mk) {
#pragma unroll
                for (int q = 0; q < NPQ; q++) {
                    float4 r = p[q];
                    r.x = r.x * 30.0f - 15.0f;
                    r.y = r.y * 60.0f - 30.0f;
                    r.z = r.z * 30.0f - 15.0f;
                    r.w = r.w * 60.0f - 30.0f;
                    dst[q] = r;
                }
            } else {
                float4 z = make_float4(0.0f, 0.0f, 0.0f, 0.0f);
#pragma unroll
                for (int q = 0; q < NPQ; q++) dst[q] = z;
            }
        }
    }

    // ---- remaining strips (only if C > NT; rare) ----
    for (int i = t + NT; i < C; i += NT) {
        const unsigned long long me = cand[i];
        int rank = 0;
        for (int jj = 0; jj < C; jj++) rank += (cand[jj] > me);

        if (rank < TOPK) {
            unsigned int mono = (unsigned int)(me >> 32);
            unsigned int u = (mono & 0x80000000u) ? (mono ^ 0x80000000u) : ~mono;
            float f = __uint_as_float(u);
            float score = 1.0f / (1.0f + __expf(-f));
            int   g   = (int)(0xFFFFFFFFu - (unsigned int)me);
            int   bi  = g / NC;
            int   lab = g - bi * NC;

            float4 bv = *(const float4*)(bbp + (size_t)bi * 4);
            float x1 = (bv.x - 0.5f * bv.z) * 30.0f - 15.0f;
            float y1 = (bv.y - 0.5f * bv.w) * 60.0f - 30.0f;
            float x2 = (bv.x + 0.5f * bv.z) * 30.0f - 15.0f;
            float y2 = (bv.y + 0.5f * bv.w) * 60.0f - 30.0f;

            bool mk = (x1 >= -20.0f) && (y1 >= -35.0f) && (x2 >= -20.0f) && (y2 >= -35.0f) &&
                      (x1 <=  20.0f) && (y1 <=  35.0f) && (x2 <=  20.0f) && (y2 <=  35.0f);

            if (!mk) { x1 = y1 = x2 = y2 = 0.0f; }
            float* ob = out + OFF_BOXES + (size_t)(b * TOPK + rank) * 4;
            ob[0] = x1; ob[1] = y1; ob[2] = x2; ob[3] = y2;
            out[OFF_SCORES + b * TOPK + rank] = mk ? score : 0.0f;
            out[OFF_LABELS + b * TOPK + rank] = mk ? (float)lab : -1.0f;
            out[OFF_MASK   + b * TOPK + rank] = mk ? 1.0f : 0.0f;

            const float4* src = pp4 + (size_t)bi * NPQ;
            float4*       dst = op4 + (size_t)rank * NPQ;
            if (mk) {
#pragma unroll
                for (int q = 0; q < NPQ; q++) {
                    float4 r = src[q];
                    r.x = r.x * 30.0f - 15.0f;
                    r.y = r.y * 60.0f - 30.0f;
                    r.z = r.z * 30.0f - 15.0f;
                    r.w = r.w * 60.0f - 30.0f;
                    dst[q] = r;
                }
            } else {
                float4 z = make_float4(0.0f, 0.0f, 0.0f, 0.0f);
#pragma unroll
                for (int q = 0; q < NPQ; q++) dst[q] = z;
            }
        }
    }
}

extern "C" void kernel_launch(void* const* d_in, const int* in_sizes, int n_in,
                              void* d_out, int out_size)
{
    const float* cls = nullptr;
    const float* bb  = nullptr;
    const float* pt  = nullptr;
    for (int i = 0; i < n_in; i++) {
        if      (in_sizes[i] == 4608000)  cls = (const float*)d_in[i];
        else if (in_sizes[i] == 6144000)  bb  = (const float*)d_in[i];
        else if (in_sizes[i] == 61440000) pt  = (const float*)d_in[i];
    }
    if (!cls && n_in > 0) cls = (const float*)d_in[0];
    if (!bb  && n_in > 1) bb  = (const float*)d_in[1];
    if (!pt  && n_in > 2) pt  = (const float*)d_in[2];

    maptr_post_kernel<<<BATCH, NT>>>(cls, bb, pt, (float*)d_out);
    (void)out_size;
}